// round 1
// baseline (speedup 1.0000x reference)
#include <cuda_runtime.h>
#include <math.h>

#define N_NODES 8192
#define F_IN    256
#define F_OUT   64

// Scratch (allocation-free rule: __device__ globals)
__device__ float g_fts[(size_t)N_NODES * F_OUT];
__device__ float g_f1[N_NODES];
__device__ float g_f2[N_NODES];

// ---------------------------------------------------------------------------
// Kernel 1: fts = x @ W   (8192x256 @ 256x64, fp32)
// Block: 64 nodes x 64 features, 256 threads, each thread a 4x4 microtile.
// ---------------------------------------------------------------------------
#define GN 64
#define KB 32

__global__ void __launch_bounds__(256) gemm_kernel(const float* __restrict__ x,
                                                   const float* __restrict__ W) {
    __shared__ float xs[KB][GN + 4];   // xs[k][n], padded row (68 floats, 16B-aligned rows)
    __shared__ float ws[KB][F_OUT];    // ws[k][f]

    const int tid = threadIdx.x;
    const int n0  = blockIdx.x * GN;
    const int tn  = tid & 15;          // node quad
    const int tf  = tid >> 4;          // feature quad

    float acc[4][4] = {};

    for (int kb = 0; kb < F_IN; kb += KB) {
        // load x tile (64 nodes x 32 k), transposed into xs[k][n]
        #pragma unroll
        for (int r = 0; r < 2; r++) {
            int idx = tid + r * 256;           // 0..511 float4 slots
            int n   = idx >> 3;                // 0..63
            int kq  = idx & 7;                 // 0..7
            float4 v = *reinterpret_cast<const float4*>(
                &x[(size_t)(n0 + n) * F_IN + kb + kq * 4]);
            xs[kq * 4 + 0][n] = v.x;
            xs[kq * 4 + 1][n] = v.y;
            xs[kq * 4 + 2][n] = v.z;
            xs[kq * 4 + 3][n] = v.w;
        }
        // load W tile (32 k x 64 f), straight copy
        #pragma unroll
        for (int r = 0; r < 2; r++) {
            int idx = tid + r * 256;           // 0..511 float4 slots over [32][64]
            int k   = idx >> 4;
            int fq  = idx & 15;
            *reinterpret_cast<float4*>(&ws[k][fq * 4]) =
                *reinterpret_cast<const float4*>(&W[(size_t)(kb + k) * F_OUT + fq * 4]);
        }
        __syncthreads();

        #pragma unroll
        for (int k = 0; k < KB; k++) {
            float4 xv = *reinterpret_cast<const float4*>(&xs[k][tn * 4]);
            float4 wv = *reinterpret_cast<const float4*>(&ws[k][tf * 4]);
            float xr[4] = {xv.x, xv.y, xv.z, xv.w};
            float wr[4] = {wv.x, wv.y, wv.z, wv.w};
            #pragma unroll
            for (int i = 0; i < 4; i++)
                #pragma unroll
                for (int j = 0; j < 4; j++)
                    acc[i][j] += xr[i] * wr[j];
        }
        __syncthreads();
    }

    #pragma unroll
    for (int i = 0; i < 4; i++) {
        int n = n0 + tn * 4 + i;
        float4 v = make_float4(acc[i][0], acc[i][1], acc[i][2], acc[i][3]);
        *reinterpret_cast<float4*>(&g_fts[(size_t)n * F_OUT + tf * 4]) = v;
    }
}

// ---------------------------------------------------------------------------
// Kernel 2: f1[n] = fts[n,:]@a1 + b1 ; f2[n] = fts[n,:]@a2 + b2
// One warp per node, shfl reduction.
// ---------------------------------------------------------------------------
__global__ void __launch_bounds__(256) proj_kernel(const float* __restrict__ a1,
                                                   const float* __restrict__ b1,
                                                   const float* __restrict__ a2,
                                                   const float* __restrict__ b2) {
    int gwarp = (blockIdx.x * blockDim.x + threadIdx.x) >> 5;
    int lane  = threadIdx.x & 31;
    if (gwarp >= N_NODES) return;

    const float* row = &g_fts[(size_t)gwarp * F_OUT];
    float v0 = row[lane], v1 = row[lane + 32];
    float s1 = v0 * a1[lane] + v1 * a1[lane + 32];
    float s2 = v0 * a2[lane] + v1 * a2[lane + 32];
    #pragma unroll
    for (int o = 16; o > 0; o >>= 1) {
        s1 += __shfl_xor_sync(0xffffffffu, s1, o);
        s2 += __shfl_xor_sync(0xffffffffu, s2, o);
    }
    if (lane == 0) {
        g_f1[gwarp] = s1 + b1[0];
        g_f2[gwarp] = s2 + b2[0];
    }
}

// ---------------------------------------------------------------------------
// Kernel 3: per-row attention. One CTA of 256 threads per row.
//   pass 1: scan adj row (float4, coalesced), scores -> smem, block max
//   pass 2: w = exp(s - max), sum, compact nonzero-w indices to u16 list
//   pass 3: 64 feature-owners x 4 chunks accumulate  sum_j w_j * fts[j][f]
// Smem: 8192 floats (scores, overwritten by w) + 8192 u16 (index list) = 48KB
// ---------------------------------------------------------------------------
#define SMEM_MAIN_BYTES (N_NODES * 4 + N_NODES * 2)

__global__ void __launch_bounds__(256) attn_kernel(const float* __restrict__ adj,
                                                   const float* __restrict__ bias,
                                                   float* __restrict__ out) {
    extern __shared__ unsigned char smem_raw[];
    float*          s_scores = reinterpret_cast<float*>(smem_raw);               // [8192]
    unsigned short* s_jlist  = reinterpret_cast<unsigned short*>(smem_raw + N_NODES * 4); // [8192]

    __shared__ float red[8];
    __shared__ float part[4][F_OUT];
    __shared__ int   s_cnt;
    __shared__ float s_stat[2];   // [0]=max, [1]=sum

    const int tid = threadIdx.x;
    const int row = blockIdx.x;

    const float4* arow4 = reinterpret_cast<const float4*>(adj + (size_t)row * N_NODES);
    const float4* f2v4  = reinterpret_cast<const float4*>(g_f2);
    const float   f1i   = g_f1[row];

    if (tid == 0) s_cnt = 0;

    // ---- pass 1: scores + local max ----
    float lmax = -3.4e38f;
    #pragma unroll
    for (int k = 0; k < 8; k++) {
        int j4 = tid + k * 256;
        float4 a4 = arow4[j4];
        float4 f2 = f2v4[j4];
        float t0 = f1i + f2.x; t0 = (t0 > 0.f ? t0 : 0.2f * t0) + a4.x;
        float t1 = f1i + f2.y; t1 = (t1 > 0.f ? t1 : 0.2f * t1) + a4.y;
        float t2 = f1i + f2.z; t2 = (t2 > 0.f ? t2 : 0.2f * t2) + a4.z;
        float t3 = f1i + f2.w; t3 = (t3 > 0.f ? t3 : 0.2f * t3) + a4.w;
        int jb = j4 * 4;
        s_scores[jb + 0] = t0;
        s_scores[jb + 1] = t1;
        s_scores[jb + 2] = t2;
        s_scores[jb + 3] = t3;
        lmax = fmaxf(lmax, fmaxf(fmaxf(t0, t1), fmaxf(t2, t3)));
    }
    // deterministic block max
    #pragma unroll
    for (int o = 16; o > 0; o >>= 1)
        lmax = fmaxf(lmax, __shfl_xor_sync(0xffffffffu, lmax, o));
    if ((tid & 31) == 0) red[tid >> 5] = lmax;
    __syncthreads();
    if (tid == 0) {
        float m = red[0];
        #pragma unroll
        for (int w = 1; w < 8; w++) m = fmaxf(m, red[w]);
        s_stat[0] = m;
    }
    __syncthreads();
    const float bmax = s_stat[0];

    // ---- pass 2: exp, sum, compact nonzeros ----
    float lsum = 0.f;
    #pragma unroll
    for (int k = 0; k < 8; k++) {
        int jb = (tid + k * 256) * 4;
        #pragma unroll
        for (int c = 0; c < 4; c++) {
            int j = jb + c;
            float w = expf(s_scores[j] - bmax);
            s_scores[j] = w;
            lsum += w;
            if (w > 0.f) {
                int p = atomicAdd(&s_cnt, 1);
                s_jlist[p] = (unsigned short)j;
            }
        }
    }
    #pragma unroll
    for (int o = 16; o > 0; o >>= 1)
        lsum += __shfl_xor_sync(0xffffffffu, lsum, o);
    if ((tid & 31) == 0) red[tid >> 5] = lsum;
    __syncthreads();
    if (tid == 0) {
        float s = red[0];
        #pragma unroll
        for (int w = 1; w < 8; w++) s += red[w];
        s_stat[1] = s;
    }
    __syncthreads();

    // ---- pass 3: sparse weighted sum of fts rows ----
    const int   M   = s_cnt;
    const float inv = 1.0f / s_stat[1];
    const int   f   = tid & 63;
    const int   c   = tid >> 6;

    float acc = 0.f;
    for (int l = c; l < M; l += 4) {
        int j = s_jlist[l];
        acc += s_scores[j] * g_fts[(size_t)j * F_OUT + f];
    }
    part[c][f] = acc;
    __syncthreads();

    if (tid < F_OUT) {
        float v = (part[0][f] + part[1][f] + part[2][f] + part[3][f]) * inv + bias[f];
        out[(size_t)row * F_OUT + f] = (v > 0.f) ? v : expm1f(v);
    }
}

// ---------------------------------------------------------------------------
// Launch
// ---------------------------------------------------------------------------
extern "C" void kernel_launch(void* const* d_in, const int* in_sizes, int n_in,
                              void* d_out, int out_size) {
    const float* x    = (const float*)d_in[0];
    const float* adj  = (const float*)d_in[1];
    const float* W    = (const float*)d_in[2];
    const float* a1   = (const float*)d_in[3];
    const float* b1   = (const float*)d_in[4];
    const float* a2   = (const float*)d_in[5];
    const float* b2   = (const float*)d_in[6];
    const float* bias = (const float*)d_in[7];
    float* out = (float*)d_out;

    gemm_kernel<<<N_NODES / GN, 256>>>(x, W);
    proj_kernel<<<(N_NODES * 32) / 256, 256>>>(a1, b1, a2, b2);

    cudaFuncSetAttribute(attn_kernel, cudaFuncAttributeMaxDynamicSharedMemorySize, 65536);
    attn_kernel<<<N_NODES, 256, SMEM_MAIN_BYTES>>>(adj, bias, out);
}

// round 5
// speedup vs baseline: 1.9146x; 1.9146x over previous
#include <cuda_runtime.h>
#include <math.h>

#define N_NODES 8192
#define F_IN    256
#define F_OUT   64

__device__ float g_fts[(size_t)N_NODES * F_OUT];
__device__ float g_f1[N_NODES];
__device__ float g_f2[N_NODES];

// ---------------------------------------------------------------------------
// Kernel 1: fts = x @ W   (8192x256 @ 256x64, fp32)
// GN=32 nodes per block -> 256 blocks (1.7 waves on 148 SMs).
// 256 threads, each computes a 2x4 (node x feat) microtile.
// ---------------------------------------------------------------------------
#define GN 32
#define KB 32

__global__ void __launch_bounds__(256) gemm_kernel(const float* __restrict__ x,
                                                   const float* __restrict__ W) {
    __shared__ float xs[KB][GN + 4];   // xs[k][n]
    __shared__ float ws[KB][F_OUT];    // ws[k][f]

    const int tid = threadIdx.x;
    const int n0  = blockIdx.x * GN;
    const int tn  = tid & 15;          // node pair (2 nodes each)
    const int tf  = tid >> 4;          // feature quad

    float acc[2][4] = {};

    for (int kb = 0; kb < F_IN; kb += KB) {
        // x tile: 32 nodes x 32 k = 256 float4, one per thread, transposed
        {
            int n  = tid >> 3;             // 0..31
            int kq = tid & 7;              // 0..7
            float4 v = *reinterpret_cast<const float4*>(
                &x[(size_t)(n0 + n) * F_IN + kb + kq * 4]);
            xs[kq * 4 + 0][n] = v.x;
            xs[kq * 4 + 1][n] = v.y;
            xs[kq * 4 + 2][n] = v.z;
            xs[kq * 4 + 3][n] = v.w;
        }
        // W tile: 32 k x 64 f = 512 float4, two per thread
        #pragma unroll
        for (int r = 0; r < 2; r++) {
            int idx = tid + r * 256;
            int k   = idx >> 4;
            int fq  = idx & 15;
            *reinterpret_cast<float4*>(&ws[k][fq * 4]) =
                *reinterpret_cast<const float4*>(&W[(size_t)(kb + k) * F_OUT + fq * 4]);
        }
        __syncthreads();

        #pragma unroll
        for (int k = 0; k < KB; k++) {
            float x0 = xs[k][tn * 2 + 0];
            float x1 = xs[k][tn * 2 + 1];
            float4 wv = *reinterpret_cast<const float4*>(&ws[k][tf * 4]);
            acc[0][0] += x0 * wv.x; acc[0][1] += x0 * wv.y;
            acc[0][2] += x0 * wv.z; acc[0][3] += x0 * wv.w;
            acc[1][0] += x1 * wv.x; acc[1][1] += x1 * wv.y;
            acc[1][2] += x1 * wv.z; acc[1][3] += x1 * wv.w;
        }
        __syncthreads();
    }

    #pragma unroll
    for (int i = 0; i < 2; i++) {
        int n = n0 + tn * 2 + i;
        float4 v = make_float4(acc[i][0], acc[i][1], acc[i][2], acc[i][3]);
        *reinterpret_cast<float4*>(&g_fts[(size_t)n * F_OUT + tf * 4]) = v;
    }
}

// ---------------------------------------------------------------------------
// Kernel 2: f1[n] = fts[n,:]@a1 + b1 ; f2[n] = fts[n,:]@a2 + b2
// ---------------------------------------------------------------------------
__global__ void __launch_bounds__(256) proj_kernel(const float* __restrict__ a1,
                                                   const float* __restrict__ b1,
                                                   const float* __restrict__ a2,
                                                   const float* __restrict__ b2) {
    int gwarp = (blockIdx.x * blockDim.x + threadIdx.x) >> 5;
    int lane  = threadIdx.x & 31;
    if (gwarp >= N_NODES) return;

    const float* row = &g_fts[(size_t)gwarp * F_OUT];
    float v0 = row[lane], v1 = row[lane + 32];
    float s1 = v0 * a1[lane] + v1 * a1[lane + 32];
    float s2 = v0 * a2[lane] + v1 * a2[lane + 32];
    #pragma unroll
    for (int o = 16; o > 0; o >>= 1) {
        s1 += __shfl_xor_sync(0xffffffffu, s1, o);
        s2 += __shfl_xor_sync(0xffffffffu, s2, o);
    }
    if (lane == 0) {
        g_f1[gwarp] = s1 + b1[0];
        g_f2[gwarp] = s2 + b2[0];
    }
}

// ---------------------------------------------------------------------------
// Kernel 3: per-row attention, sparsity-aware.
// One CTA (256 thr) per row. Single streaming pass over adj (__ldcs) + f2,
// compacting neighbors (adj==0.0f) into a tiny smem list while tracking the
// full-row max in registers. exp/sum/weighted-sum then run on ~32 entries.
// Exact dense fallback for degenerate rows (0 or >CAP neighbors).
// ---------------------------------------------------------------------------
#define CAP 1024

__global__ void __launch_bounds__(256) attn_kernel(const float* __restrict__ adj,
                                                   const float* __restrict__ bias,
                                                   float* __restrict__ out) {
    __shared__ float          s_sc[CAP];
    __shared__ unsigned short s_j[CAP];
    __shared__ float          red[8];
    __shared__ float          part[4][F_OUT];
    __shared__ int            s_cnt;
    __shared__ float          s_stat[2];   // [0]=max, [1]=sum

    const int tid = threadIdx.x;
    const int row = blockIdx.x;

    const float4* arow4 = reinterpret_cast<const float4*>(adj + (size_t)row * N_NODES);
    const float4* f2v4  = reinterpret_cast<const float4*>(g_f2);
    const float   f1i   = g_f1[row];

    if (tid == 0) s_cnt = 0;
    __syncthreads();

    // ---- pass 1: stream adj, compact neighbors, full-row max ----
    float lmax = -3.4e38f;
    #pragma unroll
    for (int k = 0; k < 8; k++) {
        int j4 = tid + k * 256;
        float4 a4 = __ldcs(&arow4[j4]);       // streaming: don't pollute L1
        float4 f2 = f2v4[j4];                 // L1-resident (32KB vector)
        float t0 = f1i + f2.x; t0 = (t0 > 0.f ? t0 : 0.2f * t0);
        float t1 = f1i + f2.y; t1 = (t1 > 0.f ? t1 : 0.2f * t1);
        float t2 = f1i + f2.z; t2 = (t2 > 0.f ? t2 : 0.2f * t2);
        float t3 = f1i + f2.w; t3 = (t3 > 0.f ? t3 : 0.2f * t3);
        lmax = fmaxf(lmax, fmaxf(fmaxf(t0 + a4.x, t1 + a4.y),
                                 fmaxf(t2 + a4.z, t3 + a4.w)));
        int jb = j4 * 4;
        if (a4.x == 0.0f) { int p = atomicAdd(&s_cnt, 1); if (p < CAP) { s_j[p] = (unsigned short)(jb + 0); s_sc[p] = t0; } }
        if (a4.y == 0.0f) { int p = atomicAdd(&s_cnt, 1); if (p < CAP) { s_j[p] = (unsigned short)(jb + 1); s_sc[p] = t1; } }
        if (a4.z == 0.0f) { int p = atomicAdd(&s_cnt, 1); if (p < CAP) { s_j[p] = (unsigned short)(jb + 2); s_sc[p] = t2; } }
        if (a4.w == 0.0f) { int p = atomicAdd(&s_cnt, 1); if (p < CAP) { s_j[p] = (unsigned short)(jb + 3); s_sc[p] = t3; } }
    }
    #pragma unroll
    for (int o = 16; o > 0; o >>= 1)
        lmax = fmaxf(lmax, __shfl_xor_sync(0xffffffffu, lmax, o));
    if ((tid & 31) == 0) red[tid >> 5] = lmax;
    __syncthreads();
    if (tid == 0) {
        float m = red[0];
        #pragma unroll
        for (int w = 1; w < 8; w++) m = fmaxf(m, red[w]);
        s_stat[0] = m;
    }
    __syncthreads();
    const float bmax = s_stat[0];
    const int   M    = s_cnt;
    const int   f    = tid & 63;
    const int   c    = tid >> 6;

    if (M > 0 && M <= CAP) {
        // ---- sparse path: exp + sum over M entries ----
        float lsum = 0.f;
        for (int l = tid; l < M; l += 256) {
            float w = expf(s_sc[l] - bmax);
            s_sc[l] = w;
            lsum += w;
        }
        #pragma unroll
        for (int o = 16; o > 0; o >>= 1)
            lsum += __shfl_xor_sync(0xffffffffu, lsum, o);
        if ((tid & 31) == 0) red[tid >> 5] = lsum;
        __syncthreads();
        if (tid == 0) {
            float s = red[0];
            #pragma unroll
            for (int w = 1; w < 8; w++) s += red[w];
            s_stat[1] = s;
        }
        __syncthreads();

        float acc = 0.f;
        for (int l = c; l < M; l += 4)
            acc += s_sc[l] * g_fts[(size_t)s_j[l] * F_OUT + f];
        part[c][f] = acc;
        __syncthreads();

        if (tid < F_OUT) {
            float v = (part[0][f] + part[1][f] + part[2][f] + part[3][f])
                      / s_stat[1] + bias[f];
            out[(size_t)row * F_OUT + f] = (v > 0.f) ? v : expm1f(v);
        }
    } else {
        // ---- exact dense fallback (degenerate rows; effectively never taken) ----
        const float* arow = adj + (size_t)row * N_NODES;
        float acc = 0.f, wsum = 0.f;
        for (int j = c; j < N_NODES; j += 4) {
            float t = f1i + g_f2[j];
            t = (t > 0.f ? t : 0.2f * t) + arow[j];
            float w = expf(t - bmax);
            wsum += w;
            acc  += w * g_fts[(size_t)j * F_OUT + f];
        }
        part[c][f] = acc;
        if (f == 0) red[c] = wsum;          // one group's wsum (all f identical)
        __syncthreads();
        if (tid < F_OUT) {
            float tot = red[0] + red[1] + red[2] + red[3];
            float v = (part[0][f] + part[1][f] + part[2][f] + part[3][f])
                      / tot + bias[f];
            out[(size_t)row * F_OUT + f] = (v > 0.f) ? v : expm1f(v);
        }
    }
}

// ---------------------------------------------------------------------------
// Launch
// ---------------------------------------------------------------------------
extern "C" void kernel_launch(void* const* d_in, const int* in_sizes, int n_in,
                              void* d_out, int out_size) {
    const float* x    = (const float*)d_in[0];
    const float* adj  = (const float*)d_in[1];
    const float* W    = (const float*)d_in[2];
    const float* a1   = (const float*)d_in[3];
    const float* b1   = (const float*)d_in[4];
    const float* a2   = (const float*)d_in[5];
    const float* b2   = (const float*)d_in[6];
    const float* bias = (const float*)d_in[7];
    float* out = (float*)d_out;

    gemm_kernel<<<N_NODES / GN, 256>>>(x, W);
    proj_kernel<<<(N_NODES * 32) / 256, 256>>>(a1, b1, a2, b2);
    attn_kernel<<<N_NODES, 256>>>(adj, bias, out);
}